// round 6
// baseline (speedup 1.0000x reference)
#include <cuda_runtime.h>
#include <math.h>

typedef unsigned long long u64;

#define THREADS 320
#define LP_BLOCKS 1024
#define MAXB 2097152

// ---------------- encoder smem layout (float offsets) ----------------
#define EW1   0          // 22 x 64
#define EB1   1408
#define ELN1G 1472
#define ELN1B 1536
#define EW2   1600       // 64 x 64
#define EB2   5696
#define ELN2G 5760
#define ELN2B 5824
#define EW3   5888       // 64 x 32
#define EB3   7936       // 32
#define ESTASH 7968      // 2 x THREADS x 65 bounce buffers
#define ENC_SM (7968 + 2 * THREADS * 65)

// ---------------- flow smem layout (float offsets) ----------------
#define FW1   0          // 33 x 64
#define FB1   2112
#define FW2   2176       // 64 x 64
#define FB2   6272
#define FW3   6336       // 64 x 24 (out padded 23->24)
#define FB3   7872       // 24 (padded)
#define FSTASH 7904      // 2 x THREADS x 65
#define FLOW_SM (7904 + 2 * THREADS * 65)

__device__ float g_z[MAXB];
__device__ float g_ladj[MAXB];
__device__ float g_block_sums[LP_BLOCKS];

// ---------------- packed f32x2 helpers ----------------
__device__ __forceinline__ u64 bcast2(float x) {
    u64 r;
    asm("mov.b64 %0, {%1, %1};" : "=l"(r) : "f"(x));
    return r;
}
__device__ __forceinline__ void fma2(u64& acc, u64 a, u64 b) {
    asm("fma.rn.f32x2 %0, %1, %2, %0;" : "+l"(acc) : "l"(a), "l"(b));
}
__device__ __forceinline__ void unpack2(u64 v, float& lo, float& hi) {
    asm("mov.b64 {%0, %1}, %2;" : "=f"(lo), "=f"(hi) : "l"(v));
}

// Two-row GEMV: one weight load feeds both rows (halves weight LDS traffic).
// Inputs in registers; outputs to per-thread smem stash (or regs).
template<int NIN, int NPAIR, int CP, bool RELU>
__device__ __forceinline__ void gemv_rb2(
    const float* __restrict__ aA, const float* __restrict__ aB,
    const float* __restrict__ W,  const float* __restrict__ bias,
    float* __restrict__ outA, float* __restrict__ outB)
{
#pragma unroll
    for (int c0 = 0; c0 < NPAIR; c0 += CP) {
        u64 accA[CP], accB[CP];
        const ulonglong2* bp =
            reinterpret_cast<const ulonglong2*>(bias + 2 * c0);
#pragma unroll
        for (int q = 0; q < CP / 2; q++) {
            ulonglong2 b2 = bp[q];
            accA[2 * q] = b2.x; accA[2 * q + 1] = b2.y;
            accB[2 * q] = b2.x; accB[2 * q + 1] = b2.y;
        }
#pragma unroll
        for (int i = 0; i < NIN; i++) {
            u64 aa = bcast2(aA[i]);
            u64 ab = bcast2(aB[i]);
            const ulonglong2* wp =
                reinterpret_cast<const ulonglong2*>(W + i * (2 * NPAIR) + 2 * c0);
#pragma unroll
            for (int q = 0; q < CP / 2; q++) {
                ulonglong2 w2 = wp[q];
                fma2(accA[2 * q],     aa, w2.x);
                fma2(accA[2 * q + 1], aa, w2.y);
                fma2(accB[2 * q],     ab, w2.x);
                fma2(accB[2 * q + 1], ab, w2.y);
            }
        }
#pragma unroll
        for (int p = 0; p < CP; p++) {
            float lo, hi;
            unpack2(accA[p], lo, hi);
            if (RELU) { lo = fmaxf(lo, 0.f); hi = fmaxf(hi, 0.f); }
            outA[2 * (c0 + p)] = lo; outA[2 * (c0 + p) + 1] = hi;
            unpack2(accB[p], lo, hi);
            if (RELU) { lo = fmaxf(lo, 0.f); hi = fmaxf(hi, 0.f); }
            outB[2 * (c0 + p)] = lo; outB[2 * (c0 + p) + 1] = hi;
        }
    }
}

template<int N>
__device__ __forceinline__ void loadNs(float* __restrict__ dst,
                                       const float* __restrict__ st) {
#pragma unroll
    for (int j = 0; j < N; j++) dst[j] = st[j];
}

__device__ __forceinline__ void ln_gelu(float* h, const float* __restrict__ g,
                                        const float* __restrict__ b) {
    float m0 = 0.f, m1 = 0.f;
#pragma unroll
    for (int j = 0; j < 64; j += 2) { m0 += h[j]; m1 += h[j + 1]; }
    float mu = (m0 + m1) * (1.f / 64.f);
    float v0 = 0.f, v1 = 0.f;
#pragma unroll
    for (int j = 0; j < 64; j += 2) {
        float d0 = h[j] - mu;      v0 = fmaf(d0, d0, v0);
        float d1 = h[j + 1] - mu;  v1 = fmaf(d1, d1, v1);
    }
    float var = (v0 + v1) * (1.f / 64.f);
    float inv = rsqrtf(var + 1e-5f);
#pragma unroll
    for (int j = 0; j < 64; j++) {
        float v = (h[j] - mu) * inv * g[j] + b[j];
        h[j] = 0.5f * v * (1.f + erff(v * 0.70710678118654752f));
    }
}

// ---------------- rational-quadratic spline (one row) ----------------
__device__ __forceinline__ void rqs_step(const float* __restrict__ p3,
                                         float& z, float& ladj) {
    const float* pw = p3;
    const float* ph = p3 + 8;
    const float* pd = p3 + 16;
    float ew[8], eh[8];
    float mw = pw[0], mh = ph[0];
#pragma unroll
    for (int n = 1; n < 8; n++) {
        mw = fmaxf(mw, pw[n]); mh = fmaxf(mh, ph[n]);
    }
    float sw = 0.f, sh = 0.f;
#pragma unroll
    for (int n = 0; n < 8; n++) {
        ew[n] = __expf(pw[n] - mw); sw += ew[n];
        eh[n] = __expf(ph[n] - mh); sh += eh[n];
    }
    float aw = __fdividef(10.0f, sw), ah = __fdividef(10.0f, sh);
    float xk[9], yk[9], dk[9];
    xk[0] = -5.f; yk[0] = -5.f; dk[0] = 1.f; dk[8] = 1.f;
#pragma unroll
    for (int n = 0; n < 8; n++) {
        xk[n + 1] = fmaf(ew[n], aw, xk[n]);
        yk[n + 1] = fmaf(eh[n], ah, yk[n]);
    }
#pragma unroll
    for (int n = 0; n < 7; n++) {
        float v = pd[n];
        dk[n + 1] = fmaxf(v, 0.f) + log1pf(__expf(-fabsf(v)));
    }
    bool inside = (z > -5.f) && (z < 5.f);
    float xc = fminf(fmaxf(z, -5.f), 5.f);
    float x0 = xk[0], x1 = xk[1], y0 = yk[0], y1 = yk[1];
    float d0 = dk[0], d1 = dk[1];
#pragma unroll
    for (int m = 1; m < 8; m++) {
        bool cc = xc >= xk[m];
        x0 = cc ? xk[m] : x0;     x1 = cc ? xk[m + 1] : x1;
        y0 = cc ? yk[m] : y0;     y1 = cc ? yk[m + 1] : y1;
        d0 = cc ? dk[m] : d0;     d1 = cc ? dk[m + 1] : d1;
    }
    float wk = x1 - x0, hk = y1 - y0;
    float s  = __fdividef(hk, wk);
    float xi = __fdividef(xc - x0, wk);
    float om = 1.f - xi;
    float den = fmaf(fmaf(-2.f, s, d0 + d1), xi * om, s);
    float yin = y0 + hk * __fdividef(s * xi * xi + d0 * xi * om, den);
    float A   = fmaf(d1 * xi, xi, fmaf(2.f * s * xi, om, d0 * om * om));
    float ldin = __logf(__fdividef((s * s) * A, den * den));
    z    = inside ? yin : z;
    ladj = inside ? (ladj + ldin) : ladj;
}

__global__ void nudge_kernel(int) {}

// ======================= encoder =======================
__global__ __launch_bounds__(THREADS, 1)
void encoder_kernel(
    const float* __restrict__ metadata, const float* __restrict__ mask,
    const float* __restrict__ eW1, const float* __restrict__ eb1,
    const float* __restrict__ eg1, const float* __restrict__ ebt1,
    const float* __restrict__ eW2, const float* __restrict__ eb2,
    const float* __restrict__ eg2, const float* __restrict__ ebt2,
    const float* __restrict__ eW3, const float* __restrict__ eb3,
    float* __restrict__ out_latent, int B)
{
    extern __shared__ float sm[];
    const int tid = threadIdx.x;
    for (int idx = tid; idx < 22 * 64; idx += THREADS) sm[EW1 + idx] = eW1[idx];
    for (int idx = tid; idx < 64; idx += THREADS) {
        sm[EB1 + idx] = eb1[idx];  sm[ELN1G + idx] = eg1[idx];
        sm[ELN1B + idx] = ebt1[idx];
        sm[EB2 + idx] = eb2[idx];  sm[ELN2G + idx] = eg2[idx];
        sm[ELN2B + idx] = ebt2[idx];
    }
    for (int idx = tid; idx < 64 * 64; idx += THREADS) sm[EW2 + idx] = eW2[idx];
    for (int idx = tid; idx < 64 * 32; idx += THREADS) sm[EW3 + idx] = eW3[idx];
    for (int idx = tid; idx < 32; idx += THREADS)      sm[EB3 + idx] = eb3[idx];
    __syncthreads();

    float* __restrict__ stA = sm + ESTASH + tid * 65;
    float* __restrict__ stB = stA + THREADS * 65;

    for (int base = blockIdx.x * (2 * THREADS); base < B;
         base += gridDim.x * (2 * THREADS)) {
        int r0 = base + tid, r1 = base + THREADS + tid;
        bool v0 = r0 < B, v1 = r1 < B;

        float xA[22], xB[22];
#pragma unroll
        for (int i = 0; i < 11; i++) {
            xA[i]      = v0 ? __ldg(metadata + (size_t)r0 * 11 + i) : 0.f;
            xA[11 + i] = v0 ? __ldg(mask + (size_t)r0 * 11 + i) : 0.f;
            xB[i]      = v1 ? __ldg(metadata + (size_t)r1 * 11 + i) : 0.f;
            xB[11 + i] = v1 ? __ldg(mask + (size_t)r1 * 11 + i) : 0.f;
        }
        gemv_rb2<22, 32, 8, false>(xA, xB, sm + EW1, sm + EB1, stA, stB);
        float hA[64], hB[64];
        loadNs<64>(hA, stA); loadNs<64>(hB, stB);
        ln_gelu(hA, sm + ELN1G, sm + ELN1B);
        ln_gelu(hB, sm + ELN1G, sm + ELN1B);

        gemv_rb2<64, 32, 8, false>(hA, hB, sm + EW2, sm + EB2, stA, stB);
        loadNs<64>(hA, stA); loadNs<64>(hB, stB);
        ln_gelu(hA, sm + ELN2G, sm + ELN2B);
        ln_gelu(hB, sm + ELN2G, sm + ELN2B);

        gemv_rb2<64, 16, 8, false>(hA, hB, sm + EW3, sm + EB3, stA, stB);
        if (v0) {
            float4* o = reinterpret_cast<float4*>(out_latent + (size_t)r0 * 32);
#pragma unroll
            for (int q = 0; q < 8; q++)
                o[q] = make_float4(stA[4 * q], stA[4 * q + 1],
                                   stA[4 * q + 2], stA[4 * q + 3]);
        }
        if (v1) {
            float4* o = reinterpret_cast<float4*>(out_latent + (size_t)r1 * 32);
#pragma unroll
            for (int q = 0; q < 8; q++)
                o[q] = make_float4(stB[4 * q], stB[4 * q + 1],
                                   stB[4 * q + 2], stB[4 * q + 3]);
        }
    }
}

// ======================= one flow transform =======================
__global__ __launch_bounds__(THREADS, 1)
void flow_kernel(
    const float* __restrict__ latent, const float* __restrict__ prot,
    const float* __restrict__ age,
    const float* __restrict__ fW1t, const float* __restrict__ fb1t,
    const float* __restrict__ fW2t, const float* __restrict__ fb2t,
    const float* __restrict__ fW3t, const float* __restrict__ fb3t,
    int first, int B)
{
    extern __shared__ float sm[];
    const int tid = threadIdx.x;
    for (int idx = tid; idx < 33 * 64; idx += THREADS) sm[FW1 + idx] = fW1t[idx];
    for (int idx = tid; idx < 64; idx += THREADS) {
        sm[FB1 + idx] = fb1t[idx];
        sm[FB2 + idx] = fb2t[idx];
    }
    for (int idx = tid; idx < 64 * 64; idx += THREADS) sm[FW2 + idx] = fW2t[idx];
    for (int idx = tid; idx < 64 * 24; idx += THREADS) {
        int i = idx / 24, n = idx % 24;
        sm[FW3 + idx] = (n < 23) ? fW3t[i * 23 + n] : 0.f;
    }
    for (int idx = tid; idx < 24; idx += THREADS)
        sm[FB3 + idx] = (idx < 23) ? fb3t[idx] : 0.f;
    __syncthreads();

    float* __restrict__ stA = sm + FSTASH + tid * 65;
    float* __restrict__ stB = stA + THREADS * 65;

    for (int base = blockIdx.x * (2 * THREADS); base < B;
         base += gridDim.x * (2 * THREADS)) {
        int r0 = base + tid, r1 = base + THREADS + tid;
        bool v0 = r0 < B, v1 = r1 < B;

        float cA[33], cB[33];
#pragma unroll
        for (int q = 0; q < 8; q++) {
            float4 a = v0 ? reinterpret_cast<const float4*>(
                                latent + (size_t)r0 * 32)[q]
                          : make_float4(0.f, 0.f, 0.f, 0.f);
            cA[4 * q] = a.x; cA[4 * q + 1] = a.y;
            cA[4 * q + 2] = a.z; cA[4 * q + 3] = a.w;
            float4 b = v1 ? reinterpret_cast<const float4*>(
                                latent + (size_t)r1 * 32)[q]
                          : make_float4(0.f, 0.f, 0.f, 0.f);
            cB[4 * q] = b.x; cB[4 * q + 1] = b.y;
            cB[4 * q + 2] = b.z; cB[4 * q + 3] = b.w;
        }
        cA[32] = v0 ? __ldg(prot + r0) : 0.f;
        cB[32] = v1 ? __ldg(prot + r1) : 0.f;

        // F1: ctx(regs) -> stash
        gemv_rb2<33, 32, 8, true>(cA, cB, sm + FW1, sm + FB1, stA, stB);
        float pA[64], pB[64];
        loadNs<64>(pA, stA); loadNs<64>(pB, stB);

        // F2: regs -> stash
        gemv_rb2<64, 32, 8, true>(pA, pB, sm + FW2, sm + FB2, stA, stB);
        loadNs<64>(pA, stA); loadNs<64>(pB, stB);

        // F3: regs -> stash (keeps inputs+outputs from coexisting in regs)
        gemv_rb2<64, 12, 6, false>(pA, pB, sm + FW3, sm + FB3, stA, stB);

        float p3A[24], p3B[24];
        loadNs<24>(p3A, stA); loadNs<24>(p3B, stB);

        float zA = 0.f, zB = 0.f, lA = 0.f, lB = 0.f;
        if (first) {
            if (v0) zA = __ldg(age + r0);
            if (v1) zB = __ldg(age + r1);
        } else {
            if (v0) { zA = g_z[r0]; lA = g_ladj[r0]; }
            if (v1) { zB = g_z[r1]; lB = g_ladj[r1]; }
        }

        rqs_step(p3A, zA, lA);
        rqs_step(p3B, zB, lB);

        if (v0) { g_z[r0] = zA; g_ladj[r0] = lA; }
        if (v1) { g_z[r1] = zB; g_ladj[r1] = lB; }
    }
}

// ======================= log_prob + reduction =======================
__global__ __launch_bounds__(256, 1)
void lp_kernel(float* __restrict__ out_lp, int B) {
    __shared__ float red[256];
    float lsum = 0.f;
    for (int row = blockIdx.x * 256 + threadIdx.x; row < B;
         row += gridDim.x * 256) {
        float z = g_z[row];
        float lp = fmaf(-0.5f, z * z, -0.91893853320467274f) + g_ladj[row];
        out_lp[row] = lp;
        lsum += lp;
    }
    red[threadIdx.x] = lsum;
    __syncthreads();
#pragma unroll
    for (int off = 128; off > 0; off >>= 1) {
        if (threadIdx.x < off) red[threadIdx.x] += red[threadIdx.x + off];
        __syncthreads();
    }
    if (threadIdx.x == 0) g_block_sums[blockIdx.x] = red[0];
}

__global__ void finalize_kernel(int B, float* __restrict__ out_nll) {
    __shared__ double red[256];
    double s = 0.0;
    for (int i = threadIdx.x; i < LP_BLOCKS; i += 256)
        s += (double)g_block_sums[i];
    red[threadIdx.x] = s;
    __syncthreads();
#pragma unroll
    for (int off = 128; off > 0; off >>= 1) {
        if (threadIdx.x < off) red[threadIdx.x] += red[threadIdx.x + off];
        __syncthreads();
    }
    if (threadIdx.x == 0)
        out_nll[0] = (float)(-red[0] / (double)B);
}

extern "C" void kernel_launch(void* const* d_in, const int* in_sizes, int n_in,
                              void* d_out, int out_size) {
    const float* metadata = (const float*)d_in[0];
    const float* prot     = (const float*)d_in[1];
    const float* age      = (const float*)d_in[2];
    const float* mask     = (const float*)d_in[3];
    const float* eW1  = (const float*)d_in[4];
    const float* eb1  = (const float*)d_in[5];
    const float* eg1  = (const float*)d_in[6];
    const float* ebt1 = (const float*)d_in[7];
    const float* eW2  = (const float*)d_in[8];
    const float* eb2  = (const float*)d_in[9];
    const float* eg2  = (const float*)d_in[10];
    const float* ebt2 = (const float*)d_in[11];
    const float* eW3  = (const float*)d_in[12];
    const float* eb3  = (const float*)d_in[13];
    const float* fW1  = (const float*)d_in[14];
    const float* fb1  = (const float*)d_in[15];
    const float* fW2  = (const float*)d_in[16];
    const float* fb2  = (const float*)d_in[17];
    const float* fW3  = (const float*)d_in[18];
    const float* fb3  = (const float*)d_in[19];

    const int B = in_sizes[1];
    float* out = (float*)d_out;
    float* out_latent = out;
    float* out_lp     = out + (size_t)B * 32;
    float* out_nll    = out + (size_t)B * 33;

    int sms = 148;
    cudaDeviceProp prop;
    if (cudaGetDeviceProperties(&prop, 0) == cudaSuccess)
        sms = prop.multiProcessorCount;

    size_t enc_smem  = (size_t)ENC_SM * sizeof(float);
    size_t flow_smem = (size_t)FLOW_SM * sizeof(float);
    cudaFuncSetAttribute(encoder_kernel,
                         cudaFuncAttributeMaxDynamicSharedMemorySize,
                         (int)enc_smem);
    cudaFuncSetAttribute(flow_kernel,
                         cudaFuncAttributeMaxDynamicSharedMemorySize,
                         (int)flow_smem);

    // launch idx map: 0 nudge, 1 enc, 2 f0, 3 f1, 4 f2, 5 f3 (<- ncu -s 5),
    // 6 lp, 7 finalize
    nudge_kernel<<<1, 32>>>(0);

    encoder_kernel<<<sms, THREADS, enc_smem>>>(
        metadata, mask, eW1, eb1, eg1, ebt1, eW2, eb2, eg2, ebt2, eW3, eb3,
        out_latent, B);

    for (int t = 0; t < 4; t++) {
        flow_kernel<<<sms, THREADS, flow_smem>>>(
            out_latent, prot, age,
            fW1 + (size_t)t * 33 * 64, fb1 + (size_t)t * 64,
            fW2 + (size_t)t * 64 * 64, fb2 + (size_t)t * 64,
            fW3 + (size_t)t * 64 * 23, fb3 + (size_t)t * 23,
            (t == 0) ? 1 : 0, B);
    }

    lp_kernel<<<LP_BLOCKS, 256>>>(out_lp, B);
    finalize_kernel<<<1, 256>>>(B, out_nll);
}

// round 7
// speedup vs baseline: 2.9766x; 2.9766x over previous
#include <cuda_runtime.h>
#include <math.h>
#include <stdint.h>

#define THREADS 384
#define WARPS 12
#define MAXBLK 16384

// ---------------- flow smem layout (float/u32 offsets) ----------------
// weight frags (u32 tf32): per transform 8192 (F1:8*5*64=2560, F2:8*8*64=4096,
// F3:3*8*64=1536), 4 transforms
#define FWF    0
#define FBIAS  32768        // 4 x 160  (fb1[64], fb2[64], fb3[24 pad 32])
#define FCTX   33408        // WARPS x 16 x 44
#define FWORK  41856        // WARPS x 16 x 68
#define FRED   54912        // THREADS
#define FLOW_SMF 55296      // floats (221184 B)

// ---------------- encoder smem layout ----------------
// frags: L1 8*3*64=1536, L2 8*8*64=4096, L3 4*8*64=2048 -> 7680
#define EWF    0
#define EPAR   7680         // b1,g1,bb1,b2,g2,bb2 (64 each), b3(32) = 416
#define EIN    8096         // WARPS x 16 x 28
#define EWORK  13472        // WARPS x 16 x 68
#define ENC_SMF 26528       // floats (106112 B)

__device__ float g_block_sums[MAXBLK];

// ---------------- tf32 mma helpers ----------------
__device__ __forceinline__ uint32_t f2tf(float x) {
    uint32_t r;
    asm("cvt.rna.tf32.f32 %0, %1;" : "=r"(r) : "f"(x));
    return r;
}
__device__ __forceinline__ void mma_tf32(
    float& c0, float& c1, float& c2, float& c3,
    uint32_t a0, uint32_t a1, uint32_t a2, uint32_t a3,
    uint32_t b0, uint32_t b1)
{
    asm volatile(
        "mma.sync.aligned.m16n8k8.row.col.f32.tf32.tf32.f32 "
        "{%0,%1,%2,%3}, {%4,%5,%6,%7}, {%8,%9}, {%0,%1,%2,%3};\n"
        : "+f"(c0), "+f"(c1), "+f"(c2), "+f"(c3)
        : "r"(a0), "r"(a1), "r"(a2), "r"(a3), "r"(b0), "r"(b1));
}

// Load A fragments for KS k-steps from a warp-private fp32 tile.
template<int KS>
__device__ __forceinline__ void load_af(uint32_t a[KS][4],
                                        const float* __restrict__ t,
                                        int RS, int g, int tg) {
#pragma unroll
    for (int ks = 0; ks < KS; ks++) {
        a[ks][0] = f2tf(t[g * RS + ks * 8 + tg]);
        a[ks][1] = f2tf(t[(g + 8) * RS + ks * 8 + tg]);
        a[ks][2] = f2tf(t[g * RS + ks * 8 + tg + 4]);
        a[ks][3] = f2tf(t[(g + 8) * RS + ks * 8 + tg + 4]);
    }
}

// GEMM with bias (+optional ReLU), store straight to tile.
template<int KS, int NT, bool RELU>
__device__ __forceinline__ void gemm_store(const uint32_t a[KS][4],
                                           const uint32_t* __restrict__ wf,
                                           const float* __restrict__ bias,
                                           float* __restrict__ out,
                                           int RS, int lane, int g, int tg) {
#pragma unroll
    for (int nt = 0; nt < NT; nt++) {
        int colb = nt * 8 + 2 * tg;
        float2 bb = *(const float2*)&bias[colb];
        float c0 = bb.x, c1 = bb.y, c2 = bb.x, c3 = bb.y;
        const uint32_t* wfn = wf + nt * KS * 64;
#pragma unroll
        for (int ks = 0; ks < KS; ks++) {
            uint32_t b0 = wfn[ks * 64 + lane];
            uint32_t b1 = wfn[ks * 64 + 32 + lane];
            mma_tf32(c0, c1, c2, c3,
                     a[ks][0], a[ks][1], a[ks][2], a[ks][3], b0, b1);
        }
        if (RELU) {
            c0 = fmaxf(c0, 0.f); c1 = fmaxf(c1, 0.f);
            c2 = fmaxf(c2, 0.f); c3 = fmaxf(c3, 0.f);
        }
        *(float2*)&out[g * RS + colb] = make_float2(c0, c1);
        *(float2*)&out[(g + 8) * RS + colb] = make_float2(c2, c3);
    }
}

// GEMM keeping accumulators in registers (for LN epilogue).
template<int KS, int NT>
__device__ __forceinline__ void gemm_acc(const uint32_t a[KS][4],
                                         const uint32_t* __restrict__ wf,
                                         const float* __restrict__ bias,
                                         float acc[NT][4],
                                         int lane, int tg) {
#pragma unroll
    for (int nt = 0; nt < NT; nt++) {
        int colb = nt * 8 + 2 * tg;
        float2 bb = *(const float2*)&bias[colb];
        acc[nt][0] = bb.x; acc[nt][1] = bb.y;
        acc[nt][2] = bb.x; acc[nt][3] = bb.y;
        const uint32_t* wfn = wf + nt * KS * 64;
#pragma unroll
        for (int ks = 0; ks < KS; ks++) {
            uint32_t b0 = wfn[ks * 64 + lane];
            uint32_t b1 = wfn[ks * 64 + 32 + lane];
            mma_tf32(acc[nt][0], acc[nt][1], acc[nt][2], acc[nt][3],
                     a[ks][0], a[ks][1], a[ks][2], a[ks][3], b0, b1);
        }
    }
}

__device__ __forceinline__ float gelu_exact(float v) {
    return 0.5f * v * (1.f + erff(v * 0.70710678118654752f));
}

// In-register LayerNorm over 64 cols (rows g and g+8) via quad shuffles,
// then exact GELU, then store to tile.
__device__ __forceinline__ void ln_gelu_store(float acc[8][4],
                                              const float* __restrict__ lg,
                                              const float* __restrict__ lb,
                                              float* __restrict__ out,
                                              int RS, int g, int tg) {
    float s0 = 0.f, s1 = 0.f;
#pragma unroll
    for (int nt = 0; nt < 8; nt++) {
        s0 += acc[nt][0] + acc[nt][1];
        s1 += acc[nt][2] + acc[nt][3];
    }
    s0 += __shfl_xor_sync(0xffffffffu, s0, 1);
    s0 += __shfl_xor_sync(0xffffffffu, s0, 2);
    s1 += __shfl_xor_sync(0xffffffffu, s1, 1);
    s1 += __shfl_xor_sync(0xffffffffu, s1, 2);
    float mu0 = s0 * (1.f / 64.f), mu1 = s1 * (1.f / 64.f);
    float v0 = 0.f, v1 = 0.f;
#pragma unroll
    for (int nt = 0; nt < 8; nt++) {
        float d;
        d = acc[nt][0] - mu0; v0 = fmaf(d, d, v0);
        d = acc[nt][1] - mu0; v0 = fmaf(d, d, v0);
        d = acc[nt][2] - mu1; v1 = fmaf(d, d, v1);
        d = acc[nt][3] - mu1; v1 = fmaf(d, d, v1);
    }
    v0 += __shfl_xor_sync(0xffffffffu, v0, 1);
    v0 += __shfl_xor_sync(0xffffffffu, v0, 2);
    v1 += __shfl_xor_sync(0xffffffffu, v1, 1);
    v1 += __shfl_xor_sync(0xffffffffu, v1, 2);
    float inv0 = rsqrtf(v0 * (1.f / 64.f) + 1e-5f);
    float inv1 = rsqrtf(v1 * (1.f / 64.f) + 1e-5f);
#pragma unroll
    for (int nt = 0; nt < 8; nt++) {
        int colb = nt * 8 + 2 * tg;
        float2 gg = *(const float2*)&lg[colb];
        float2 be = *(const float2*)&lb[colb];
        float e0 = gelu_exact((acc[nt][0] - mu0) * inv0 * gg.x + be.x);
        float e1 = gelu_exact((acc[nt][1] - mu0) * inv0 * gg.y + be.y);
        float e2 = gelu_exact((acc[nt][2] - mu1) * inv1 * gg.x + be.x);
        float e3 = gelu_exact((acc[nt][3] - mu1) * inv1 * gg.y + be.y);
        *(float2*)&out[g * RS + colb] = make_float2(e0, e1);
        *(float2*)&out[(g + 8) * RS + colb] = make_float2(e2, e3);
    }
}

// ---------------- rational-quadratic spline (one row) ----------------
__device__ __forceinline__ void rqs_step(const float* __restrict__ p3,
                                         float& z, float& ladj) {
    const float* pw = p3;
    const float* ph = p3 + 8;
    const float* pd = p3 + 16;
    float ew[8], eh[8];
    float mw = pw[0], mh = ph[0];
#pragma unroll
    for (int n = 1; n < 8; n++) {
        mw = fmaxf(mw, pw[n]); mh = fmaxf(mh, ph[n]);
    }
    float sw = 0.f, sh = 0.f;
#pragma unroll
    for (int n = 0; n < 8; n++) {
        ew[n] = __expf(pw[n] - mw); sw += ew[n];
        eh[n] = __expf(ph[n] - mh); sh += eh[n];
    }
    float aw = __fdividef(10.0f, sw), ah = __fdividef(10.0f, sh);
    float xk[9], yk[9], dk[9];
    xk[0] = -5.f; yk[0] = -5.f; dk[0] = 1.f; dk[8] = 1.f;
#pragma unroll
    for (int n = 0; n < 8; n++) {
        xk[n + 1] = fmaf(ew[n], aw, xk[n]);
        yk[n + 1] = fmaf(eh[n], ah, yk[n]);
    }
#pragma unroll
    for (int n = 0; n < 7; n++) {
        float v = pd[n];
        dk[n + 1] = fmaxf(v, 0.f) + log1pf(__expf(-fabsf(v)));
    }
    bool inside = (z > -5.f) && (z < 5.f);
    float xc = fminf(fmaxf(z, -5.f), 5.f);
    float x0 = xk[0], x1 = xk[1], y0 = yk[0], y1 = yk[1];
    float d0 = dk[0], d1 = dk[1];
#pragma unroll
    for (int m = 1; m < 8; m++) {
        bool cc = xc >= xk[m];
        x0 = cc ? xk[m] : x0;     x1 = cc ? xk[m + 1] : x1;
        y0 = cc ? yk[m] : y0;     y1 = cc ? yk[m + 1] : y1;
        d0 = cc ? dk[m] : d0;     d1 = cc ? dk[m + 1] : d1;
    }
    float wk = x1 - x0, hk = y1 - y0;
    float s  = __fdividef(hk, wk);
    float xi = __fdividef(xc - x0, wk);
    float om = 1.f - xi;
    float den = fmaf(fmaf(-2.f, s, d0 + d1), xi * om, s);
    float yin = y0 + hk * __fdividef(s * xi * xi + d0 * xi * om, den);
    float A   = fmaf(d1 * xi, xi, fmaf(2.f * s * xi, om, d0 * om * om));
    float ldin = __logf(__fdividef((s * s) * A, den * den));
    z    = inside ? yin : z;
    ladj = inside ? (ladj + ldin) : ladj;
}

__global__ void nudge_kernel(int) {}

// Stage a weight matrix W[K][N] (row-major) into tf32 fragment-linear order:
// flat = ((nt*KS+ks)*2+reg)*32+lane; k = ks*8+(lane&3)+reg*4; n = nt*8+(lane>>2)
__device__ __forceinline__ void stage_frags(uint32_t* __restrict__ dst,
                                            const float* __restrict__ W,
                                            int K, int N, int KS, int NT,
                                            int tid) {
    int total = NT * KS * 64;
    for (int i = tid; i < total; i += THREADS) {
        int lane = i & 31;
        int reg  = (i >> 5) & 1;
        int rest = i >> 6;
        int ks = rest % KS, nt = rest / KS;
        int k = ks * 8 + (lane & 3) + reg * 4;
        int n = nt * 8 + (lane >> 2);
        float v = (k < K && n < N) ? W[k * N + n] : 0.f;
        dst[i] = f2tf(v);
    }
}

// ======================= encoder (tensor) =======================
__global__ __launch_bounds__(THREADS, 2)
void encoder_kernel(
    const float* __restrict__ metadata, const float* __restrict__ mask,
    const float* __restrict__ eW1, const float* __restrict__ eb1,
    const float* __restrict__ eg1, const float* __restrict__ ebt1,
    const float* __restrict__ eW2, const float* __restrict__ eb2,
    const float* __restrict__ eg2, const float* __restrict__ ebt2,
    const float* __restrict__ eW3, const float* __restrict__ eb3,
    float* __restrict__ out_latent, int B)
{
    extern __shared__ float sm[];
    uint32_t* wf = (uint32_t*)sm;
    const int tid = threadIdx.x;

    stage_frags(wf + EWF,        eW1, 22, 64, 3, 8, tid);
    stage_frags(wf + EWF + 1536, eW2, 64, 64, 8, 8, tid);
    stage_frags(wf + EWF + 5632, eW3, 64, 32, 8, 4, tid);
    for (int i = tid; i < 64; i += THREADS) {
        sm[EPAR + i]       = eb1[i];
        sm[EPAR + 64 + i]  = eg1[i];
        sm[EPAR + 128 + i] = ebt1[i];
        sm[EPAR + 192 + i] = eb2[i];
        sm[EPAR + 256 + i] = eg2[i];
        sm[EPAR + 320 + i] = ebt2[i];
    }
    for (int i = tid; i < 32; i += THREADS) sm[EPAR + 384 + i] = eb3[i];
    __syncthreads();

    const int wid = tid >> 5, lane = tid & 31;
    const int g = lane >> 2, tg = lane & 3;
    float* in   = sm + EIN   + wid * 448;   // 16 x 28
    float* work = sm + EWORK + wid * 1088;  // 16 x 68

    for (int rb = ((int)blockIdx.x * WARPS + wid) * 16; rb < B;
         rb += (int)gridDim.x * WARPS * 16) {
        // fill input tile
        for (int i = lane; i < 176; i += 32) {
            int r = i / 11, c = i % 11;
            int gr = min(rb + r, B - 1);
            in[r * 28 + c]      = metadata[(size_t)gr * 11 + c];
            in[r * 28 + 11 + c] = mask[(size_t)gr * 11 + c];
        }
        if (lane < 16) { in[lane * 28 + 22] = 0.f; in[lane * 28 + 23] = 0.f; }
        __syncwarp();

        // L1 + LN + GELU
        {
            uint32_t a3[3][4];
            load_af<3>(a3, in, 28, g, tg);
            float acc[8][4];
            gemm_acc<3, 8>(a3, wf + EWF, sm + EPAR, acc, lane, tg);
            ln_gelu_store(acc, sm + EPAR + 64, sm + EPAR + 128, work, 68, g, tg);
        }
        __syncwarp();
        // L2 + LN + GELU
        {
            uint32_t a8[8][4];
            load_af<8>(a8, work, 68, g, tg);
            float acc[8][4];
            gemm_acc<8, 8>(a8, wf + EWF + 1536, sm + EPAR + 192, acc, lane, tg);
            ln_gelu_store(acc, sm + EPAR + 256, sm + EPAR + 320, work, 68, g, tg);
        }
        __syncwarp();
        // L3 -> latent
        {
            uint32_t a8[8][4];
            load_af<8>(a8, work, 68, g, tg);
            gemm_store<8, 4, false>(a8, wf + EWF + 5632, sm + EPAR + 384,
                                    work, 68, lane, g, tg);
        }
        __syncwarp();
        for (int i = lane; i < 128; i += 32) {
            int r = i >> 3, q = i & 7;
            int gr = rb + r;
            if (gr < B)
                *(float4*)&out_latent[(size_t)gr * 32 + 4 * q] =
                    *(const float4*)&work[r * 68 + 4 * q];
        }
        __syncwarp();
    }
}

// ======================= flow: all 4 transforms (tensor) =======================
__global__ __launch_bounds__(THREADS, 1)
void flow4_kernel(
    const float* __restrict__ latent, const float* __restrict__ prot,
    const float* __restrict__ age,
    const float* __restrict__ fW1, const float* __restrict__ fb1,
    const float* __restrict__ fW2, const float* __restrict__ fb2,
    const float* __restrict__ fW3, const float* __restrict__ fb3,
    float* __restrict__ out_lp, int B)
{
    extern __shared__ float sm[];
    uint32_t* wf = (uint32_t*)sm;
    const int tid = threadIdx.x;

    for (int t = 0; t < 4; t++) {
        uint32_t* wt = wf + FWF + t * 8192;
        stage_frags(wt,        fW1 + (size_t)t * 33 * 64, 33, 64, 5, 8, tid);
        stage_frags(wt + 2560, fW2 + (size_t)t * 64 * 64, 64, 64, 8, 8, tid);
        stage_frags(wt + 6656, fW3 + (size_t)t * 64 * 23, 64, 23, 8, 3, tid);
        float* bt = sm + FBIAS + t * 160;
        for (int i = tid; i < 64; i += THREADS) {
            bt[i]      = fb1[t * 64 + i];
            bt[64 + i] = fb2[t * 64 + i];
        }
        for (int i = tid; i < 24; i += THREADS)
            bt[128 + i] = (i < 23) ? fb3[t * 23 + i] : 0.f;
    }
    __syncthreads();

    const int wid = tid >> 5, lane = tid & 31;
    const int g = lane >> 2, tg = lane & 3;
    float* ctx  = sm + FCTX  + wid * 704;   // 16 x 44
    float* work = sm + FWORK + wid * 1088;  // 16 x 68
    float lsum = 0.f;

    for (int rb = ((int)blockIdx.x * WARPS + wid) * 16; rb < B;
         rb += (int)gridDim.x * WARPS * 16) {
        // fill context tile (latent 32 + prot, pad to 40)
        for (int i = lane; i < 128; i += 32) {
            int r = i >> 3, q = i & 7;
            int gr = min(rb + r, B - 1);
            *(float4*)&ctx[r * 44 + 4 * q] =
                *(const float4*)&latent[(size_t)gr * 32 + 4 * q];
        }
        float z = 0.f, la = 0.f;
        if (lane < 16) {
            int gr = min(rb + lane, B - 1);
            ctx[lane * 44 + 32] = prot[gr];
#pragma unroll
            for (int c = 33; c < 40; c++) ctx[lane * 44 + c] = 0.f;
            z = age[gr];
        }
        __syncwarp();

        for (int t = 0; t < 4; t++) {
            const uint32_t* wt = wf + FWF + t * 8192;
            const float* bt = sm + FBIAS + t * 160;
            {
                uint32_t a5[5][4];
                load_af<5>(a5, ctx, 44, g, tg);
                gemm_store<5, 8, true>(a5, wt, bt, work, 68, lane, g, tg);
            }
            __syncwarp();
            {
                uint32_t a8[8][4];
                load_af<8>(a8, work, 68, g, tg);
                gemm_store<8, 8, true>(a8, wt + 2560, bt + 64, work, 68,
                                       lane, g, tg);
            }
            __syncwarp();
            {
                uint32_t a8[8][4];
                load_af<8>(a8, work, 68, g, tg);
                gemm_store<8, 3, false>(a8, wt + 6656, bt + 128, work, 68,
                                        lane, g, tg);
            }
            __syncwarp();
            if (lane < 16) {
                float p3[24];
#pragma unroll
                for (int c = 0; c < 24; c++) p3[c] = work[lane * 68 + c];
                rqs_step(p3, z, la);
            }
            __syncwarp();
        }

        if (lane < 16) {
            int r = rb + lane;
            if (r < B) {
                float lp = fmaf(-0.5f, z * z, -0.91893853320467274f) + la;
                out_lp[r] = lp;
                lsum += lp;
            }
        }
    }

    // block reduction of log_prob partial sums
    sm[FRED + tid] = lsum;
    __syncthreads();
#pragma unroll
    for (int off = 256; off > 0; off >>= 1) {
        if (tid < off && tid + off < THREADS)
            sm[FRED + tid] += sm[FRED + tid + off];
        __syncthreads();
    }
    if (tid == 0) g_block_sums[blockIdx.x] = sm[FRED];
}

__global__ void finalize_kernel(int nblocks, int B, float* __restrict__ out_nll) {
    __shared__ double red[256];
    double s = 0.0;
    for (int i = threadIdx.x; i < nblocks; i += 256)
        s += (double)g_block_sums[i];
    red[threadIdx.x] = s;
    __syncthreads();
#pragma unroll
    for (int off = 128; off > 0; off >>= 1) {
        if (threadIdx.x < off) red[threadIdx.x] += red[threadIdx.x + off];
        __syncthreads();
    }
    if (threadIdx.x == 0)
        out_nll[0] = (float)(-red[0] / (double)B);
}

extern "C" void kernel_launch(void* const* d_in, const int* in_sizes, int n_in,
                              void* d_out, int out_size) {
    const float* metadata = (const float*)d_in[0];
    const float* prot     = (const float*)d_in[1];
    const float* age      = (const float*)d_in[2];
    const float* mask     = (const float*)d_in[3];
    const float* eW1  = (const float*)d_in[4];
    const float* eb1  = (const float*)d_in[5];
    const float* eg1  = (const float*)d_in[6];
    const float* ebt1 = (const float*)d_in[7];
    const float* eW2  = (const float*)d_in[8];
    const float* eb2  = (const float*)d_in[9];
    const float* eg2  = (const float*)d_in[10];
    const float* ebt2 = (const float*)d_in[11];
    const float* eW3  = (const float*)d_in[12];
    const float* eb3  = (const float*)d_in[13];
    const float* fW1  = (const float*)d_in[14];
    const float* fb1  = (const float*)d_in[15];
    const float* fW2  = (const float*)d_in[16];
    const float* fb2  = (const float*)d_in[17];
    const float* fW3  = (const float*)d_in[18];
    const float* fb3  = (const float*)d_in[19];

    const int B = in_sizes[1];
    float* out = (float*)d_out;
    float* out_latent = out;
    float* out_lp     = out + (size_t)B * 32;
    float* out_nll    = out + (size_t)B * 33;

    int sms = 148;
    cudaDeviceProp prop;
    if (cudaGetDeviceProperties(&prop, 0) == cudaSuccess)
        sms = prop.multiProcessorCount;

    size_t enc_smem  = (size_t)ENC_SMF * sizeof(float);
    size_t flow_smem = (size_t)FLOW_SMF * sizeof(float);
    cudaFuncSetAttribute(encoder_kernel,
                         cudaFuncAttributeMaxDynamicSharedMemorySize,
                         (int)enc_smem);
    cudaFuncSetAttribute(flow4_kernel,
                         cudaFuncAttributeMaxDynamicSharedMemorySize,
                         (int)flow_smem);

    // launch idx: 0-3 nudges, 4 encoder, 5 flow4 (<- ncu -s 5), 6 finalize
    for (int i = 0; i < 4; i++) nudge_kernel<<<1, 32>>>(i);

    encoder_kernel<<<2 * sms, THREADS, enc_smem>>>(
        metadata, mask, eW1, eb1, eg1, ebt1, eW2, eb2, eg2, ebt2, eW3, eb3,
        out_latent, B);

    flow4_kernel<<<sms, THREADS, flow_smem>>>(
        out_latent, prot, age, fW1, fb1, fW2, fb2, fW3, fb3, out_lp, B);

    finalize_kernel<<<1, 256>>>(sms, B, out_nll);
}